// round 17
// baseline (speedup 1.0000x reference)
#include <cuda_runtime.h>
#include <cuda_fp16.h>
#include <cstdint>

// Shapes (fixed per reference setup_inputs)
#define B 2
#define S 512
#define T 512
#define D 256
#define H 128
#define BS (B*S)        // 1024
#define BT (B*T)        // 1024

#define PAD 136         // padded row stride (elems) for conflict-free ldmatrix

// Scratch (device globals; no allocation allowed)
__device__ float g_src[BS * H];       // LN(source) @ W_su + b_su (fp32)
__device__ float g_A  [BS * H];       // g_src @ W1_s + b1
__device__ __half g_th [BT * H];      // fp16 target proj

// ---------------------------------------------------------------------------
// Packed f32x2 helpers
// ---------------------------------------------------------------------------
typedef unsigned long long u64;

__device__ __forceinline__ u64 f2x_fma(u64 a, u64 b, u64 c) {
    u64 d; asm("fma.rn.f32x2 %0, %1, %2, %3;" : "=l"(d) : "l"(a), "l"(b), "l"(c));
    return d;
}
__device__ __forceinline__ u64 f2x_mul(u64 a, u64 b) {
    u64 d; asm("mul.rn.f32x2 %0, %1, %2;" : "=l"(d) : "l"(a), "l"(b));
    return d;
}
__device__ __forceinline__ u64 f2x_add(u64 a, u64 b) {
    u64 d; asm("add.rn.f32x2 %0, %1, %2;" : "=l"(d) : "l"(a), "l"(b));
    return d;
}
__device__ __forceinline__ u64 pk2(float lo, float hi) {
    u64 d; asm("mov.b64 %0, {%1, %2};" : "=l"(d) : "f"(lo), "f"(hi));
    return d;
}
__device__ __forceinline__ u64 dup2(float c) {
    u64 d; asm("mov.b64 %0, {%1, %1};" : "=l"(d) : "f"(c));
    return d;
}
__device__ __forceinline__ void upk2(float &lo, float &hi, u64 v) {
    asm("mov.b64 {%0, %1}, %2;" : "=f"(lo), "=f"(hi) : "l"(v));
}
__device__ __forceinline__ float rcp_ap(float x) {
    float r; asm("rcp.approx.f32 %0, %1;" : "=f"(r) : "f"(x));
    return r;
}
__device__ __forceinline__ float ex2_ap(float x) {
    float r; asm("ex2.approx.f32 %0, %1;" : "=f"(r) : "f"(x));
    return r;
}

// ---------------------------------------------------------------------------
// Stage 1: 8 rows per CTA, 512 threads. LN per warp (warps 0-7); projection
// splits D into 4 quarters (64 iters each) to halve serial latency.
// Grid: 256 = 128 source-CTAs + 128 target-CTAs.
// ---------------------------------------------------------------------------
#define RPB 8
#define S1THR 512

__global__ __launch_bounds__(S1THR) void norm_proj_kernel(
    const float* __restrict__ sv, const float* __restrict__ tv,
    const float* __restrict__ sng, const float* __restrict__ snb,
    const float* __restrict__ tng, const float* __restrict__ tnb,
    const float* __restrict__ Wsu, const float* __restrict__ bsu,
    const float* __restrict__ Wtp, const float* __restrict__ btp,
    const float* __restrict__ W1,  const float* __restrict__ b1)
{
    __shared__ u64  xnp[D * 5];          // [d][rp] pairs, stride-5 anti-conflict
    __shared__ u64  prp[H * 5];          // [h][rp] pairs
    __shared__ float part[4][RPB][H];

    const int cb = blockIdx.x;
    const bool is_src = cb < (BS / RPB);
    const int row0 = (is_src ? cb : cb - BS / RPB) * RPB;
    const int tid = threadIdx.x;
    const int wid = tid >> 5;
    const int lane = tid & 31;

    const float* x    = (is_src ? sv : tv) + row0 * D;
    const float* gv   = is_src ? sng : tng;
    const float* bv   = is_src ? snb : tnb;
    const float* W    = is_src ? Wsu : Wtp;
    const float* bias = is_src ? bsu : btp;

    // LN: warps 0-7, warp wid handles row (row0 + wid)
    if (wid < RPB) {
        const float* xr = x + wid * D;
        float v[8];
        float s1 = 0.f, s2 = 0.f;
        #pragma unroll
        for (int i = 0; i < 8; ++i) {
            float t = xr[lane + i * 32];
            v[i] = t; s1 += t; s2 = fmaf(t, t, s2);
        }
        #pragma unroll
        for (int m = 16; m; m >>= 1) {
            s1 += __shfl_xor_sync(0xffffffffu, s1, m);
            s2 += __shfl_xor_sync(0xffffffffu, s2, m);
        }
        const float mean = s1 * (1.0f / D);
        const float var  = s2 * (1.0f / D) - mean * mean;
        const float rs   = rsqrtf(var + 1e-5f);
        float* xf = (float*)xnp;
        #pragma unroll
        for (int i = 0; i < 8; ++i) {
            const int col = lane + i * 32;
            const float xv = (v[i] - mean) * rs * gv[col] + bv[col];
            xf[(col * 5 + (wid >> 1)) * 2 + (wid & 1)] = xv;
        }
    }
    __syncthreads();

    const int hh = tid & 127;
    const int q  = tid >> 7;             // quarter 0-3

    // Projection: quarter q covers d in [q*64, q*64+64)
    {
        u64 acc[4] = {0ULL, 0ULL, 0ULL, 0ULL};
        const float* Wp = W + (q * 64) * H + hh;
        #pragma unroll 4
        for (int d = 0; d < 64; ++d) {
            const u64 w2 = dup2(Wp[d * H]);
            const u64* xp = &xnp[(q * 64 + d) * 5];
            acc[0] = f2x_fma(xp[0], w2, acc[0]);
            acc[1] = f2x_fma(xp[1], w2, acc[1]);
            acc[2] = f2x_fma(xp[2], w2, acc[2]);
            acc[3] = f2x_fma(xp[3], w2, acc[3]);
        }
        #pragma unroll
        for (int rp = 0; rp < 4; ++rp) {
            float lo, hi; upk2(lo, hi, acc[rp]);
            part[q][2 * rp][hh]     = lo;
            part[q][2 * rp + 1][hh] = hi;
        }
    }
    __syncthreads();

    if (q == 0) {
        float* pf = (float*)prp;
        #pragma unroll
        for (int r = 0; r < RPB; ++r) {
            const float p = (part[0][r][hh] + part[1][r][hh])
                          + (part[2][r][hh] + part[3][r][hh]) + bias[hh];
            if (is_src) {
                g_src[(row0 + r) * H + hh] = p;
                pf[(hh * 5 + (r >> 1)) * 2 + (r & 1)] = p;
            } else {
                g_th[(row0 + r) * H + hh] = __float2half(p);
            }
        }
    }
    __syncthreads();

    // A = proj @ W1_s + b1 (source rows only; C-term folded into stage 2)
    if (is_src) {
        u64 acc[4] = {0ULL, 0ULL, 0ULL, 0ULL};
        const float* Wr = W1 + (q * 32) * H + hh;
        #pragma unroll 4
        for (int h = 0; h < 32; ++h) {
            const u64 w2 = dup2(Wr[h * H]);
            const u64* pp = &prp[(q * 32 + h) * 5];
            acc[0] = f2x_fma(pp[0], w2, acc[0]);
            acc[1] = f2x_fma(pp[1], w2, acc[1]);
            acc[2] = f2x_fma(pp[2], w2, acc[2]);
            acc[3] = f2x_fma(pp[3], w2, acc[3]);
        }
        #pragma unroll
        for (int rp = 0; rp < 4; ++rp) {
            float lo, hi; upk2(lo, hi, acc[rp]);
            part[q][2 * rp][hh]     = lo;
            part[q][2 * rp + 1][hh] = hi;
        }
        __syncthreads();
        if (q == 0) {
            #pragma unroll
            for (int r = 0; r < RPB; ++r)
                g_A[(row0 + r) * H + hh] =
                    (part[0][r][hh] + part[1][r][hh])
                  + (part[2][r][hh] + part[3][r][hh]) + b1[hh];
        }
    }
}

// ---------------------------------------------------------------------------
// Stage 2: mma.sync fp16 fused kernel, C-term folded into the weight.
// grid 2048: CTA = (b, s, t-half). 256 threads / 8 warps, 2 CTAs/SM.
// Epilogue gelu packed f32x2 (A-S 7.1.25 3-term erf, sign-folded).
// Epilogue combine uses per-t-group named barriers (no CTA-wide sync).
// ---------------------------------------------------------------------------
__device__ __forceinline__ void ldsm_x4(unsigned a, unsigned &r0, unsigned &r1,
                                        unsigned &r2, unsigned &r3) {
    asm volatile("ldmatrix.sync.aligned.m8n8.x4.shared.b16 {%0,%1,%2,%3}, [%4];"
        : "=r"(r0), "=r"(r1), "=r"(r2), "=r"(r3) : "r"(a));
}
__device__ __forceinline__ void ldsm_x4_t(unsigned a, unsigned &r0, unsigned &r1,
                                          unsigned &r2, unsigned &r3) {
    asm volatile("ldmatrix.sync.aligned.m8n8.x4.trans.shared.b16 {%0,%1,%2,%3}, [%4];"
        : "=r"(r0), "=r"(r1), "=r"(r2), "=r"(r3) : "r"(a));
}
__device__ __forceinline__ void mma16816(float* c, const unsigned* a,
                                         unsigned b0, unsigned b1) {
    asm volatile("mma.sync.aligned.m16n8k16.row.col.f32.f16.f16.f32 "
        "{%0,%1,%2,%3}, {%4,%5,%6,%7}, {%8,%9}, {%0,%1,%2,%3};"
        : "+f"(c[0]), "+f"(c[1]), "+f"(c[2]), "+f"(c[3])
        : "r"(a[0]), "r"(a[1]), "r"(a[2]), "r"(a[3]), "r"(b0), "r"(b1));
}
__device__ __forceinline__ void cp16(unsigned dst, const void* src) {
    asm volatile("cp.async.ca.shared.global [%0], [%1], 16;"
        :: "r"(dst), "l"(src) : "memory");
}
__device__ __forceinline__ void cp_commit() {
    asm volatile("cp.async.commit_group;" ::: "memory");
}
__device__ __forceinline__ void cp_wait0() {
    asm volatile("cp.async.wait_group 0;" ::: "memory");
}

// smem byte offsets
#define TROWS 64
#define OFF_WHI 0                          // 128*136*2 = 34816
#define OFF_TH0 34816                      // 64*136*2  = 17408
#define OFF_TH1 52224                      // 17408
#define OFF_SRC 69632                      // 128 f
#define OFF_AS  (OFF_SRC + 512)
#define OFF_W2  (OFF_AS  + 512)
#define OFF_PS  (OFF_W2  + 512)            // 64*4 f
#define SMEM_BYTES (OFF_PS + 1024)

#define NTHR 256

extern __shared__ char smem_raw[];

__global__ __launch_bounds__(NTHR, 2) void edge_main_kernel(
    const float* __restrict__ W1, const float* __restrict__ W2,
    const float* __restrict__ b2p, const int* __restrict__ mask,
    float* __restrict__ out)
{
    __half* Whi = (__half*)(smem_raw + OFF_WHI);
    float* ssrc = (float*)(smem_raw + OFF_SRC);
    float* As   = (float*)(smem_raw + OFF_AS);
    float* w2s  = (float*)(smem_raw + OFF_W2);
    float* psum = (float*)(smem_raw + OFF_PS);     // [64][4]

    unsigned smem_u32;
    asm("{ .reg .u64 t; cvta.to.shared.u64 t, %1; cvt.u32.u64 %0, t; }"
        : "=r"(smem_u32) : "l"(smem_raw));

    const int bs    = blockIdx.x >> 1;       // 0..1023
    const int thalf = blockIdx.x & 1;        // 0 or 1 (t offset 0 / 256)
    const int b     = bs >> 9;
    const int tid   = threadIdx.x;
    const int wid   = tid >> 5;
    const int lane  = tid & 31;

    // Warp tiling within 64t x 128k iteration tile: 2 t-groups x 4 k-groups
    const int grp = wid >> 2;           // t-group 0/1 (threads 0-127 / 128-255)
    const int tw0 = grp * 32;           // 0 or 32
    const int kq  = (wid & 3) * 32;     // k base
    const int rL = lane & 15;
    const int cL = (lane >> 4) << 3;
    const int gtid = tid & 127;         // index within t-group

    const int gtbase = (b << 9) + thalf * 256;

    // Prefetch Th(0) into buf0 (coalesced 16B cp.async) — overlaps prologue
    {
        const uint4* sth = (const uint4*)(g_th + gtbase * H);
        #pragma unroll
        for (int i = tid; i < TROWS * 16; i += NTHR) {
            const int row = i >> 4;
            const int c8  = i & 15;
            cp16(smem_u32 + OFF_TH0 + (row * PAD + c8 * 8) * 2, sth + i);
        }
        cp_commit();
    }

    if (tid < H) {
        ssrc[tid] = g_src[bs * H + tid];
        As[tid]   = g_A[bs * H + tid];
        w2s[tid]  = W2[tid];
    }
    __syncthreads();

    // Prologue: Whi[h][k] = fp16( src[h]*W1_st[h][k] + W1_t[h][k] ), packed
    {
        const float4* Wst4 = (const float4*)(W1 + 2 * H * H);
        const float4* Wt4  = (const float4*)(W1 + 1 * H * H);
        for (int i = tid; i < (H * H) / 4; i += NTHR) {
            const int h = i >> 5;
            const int c = (i & 31) * 4;
            const u64 sc2 = dup2(ssrc[h]);
            float4 w  = Wst4[i];
            float4 wt = Wt4[i];
            const u64 r01 = f2x_fma(pk2(w.x, w.y), sc2, pk2(wt.x, wt.y));
            const u64 r23 = f2x_fma(pk2(w.z, w.w), sc2, pk2(wt.z, wt.w));
            float f0, f1, f2, f3;
            upk2(f0, f1, r01);
            upk2(f2, f3, r23);
            *(__half2*)(Whi + h * PAD + c)     = __floats2half2_rn(f0, f1);
            *(__half2*)(Whi + h * PAD + c + 2) = __floats2half2_rn(f2, f3);
        }
    }
    __syncthreads();   // As/w2s fully written before register caching

    // Register-cache per-thread A and W2 pairs (packed f32x2, iter-invariant)
    u64 asr2[4], w2r2[4];
    #pragma unroll
    for (int g = 0; g < 4; ++g) {
        const int k = kq + g * 8 + (lane & 3) * 2;
        asr2[g] = pk2(As[k], As[k + 1]);
        w2r2[g] = pk2(w2s[k], w2s[k + 1]);
    }

    // Packed gelu constants (A-S 7.1.25 3-term, sign-folded, negated Horner)
    const u64 C_A  = dup2(0.332676f);       // 0.47047 / sqrt(2)
    const u64 C_1  = dup2(1.0f);
    const u64 C_H  = dup2(0.5f);
    const u64 C_NL = dup2(-0.72134752f);    // -log2(e)/2
    const u64 C_K1 = dup2(-0.7478556f);
    const u64 C_K2 = dup2( 0.0958798f);
    const u64 C_K3 = dup2(-0.3480242f);

    const float b2v  = b2p[0];
    const float mval = mask[bs] ? 1.0f : 0.0f;

    #pragma unroll 1
    for (int tt = 0; tt < 4; ++tt) {
        const int gt0 = gtbase + tt * TROWS;
        const unsigned thb = smem_u32 + ((tt & 1) ? OFF_TH1 : OFF_TH0);

        cp_wait0();          // Th(tt) copies issued by this thread done
        __syncthreads();     // all threads' copies visible

        // Prefetch Th(tt+1) into the other buffer (disjoint from thb)
        if (tt < 3) {
            const unsigned thn = smem_u32 + ((tt & 1) ? OFF_TH0 : OFF_TH1);
            const uint4* sth = (const uint4*)(g_th + (gt0 + TROWS) * H);
            #pragma unroll
            for (int i = tid; i < TROWS * 16; i += NTHR) {
                const int row = i >> 4;
                const int c8  = i & 15;
                cp16(thn + (row * PAD + c8 * 8) * 2, sth + i);
            }
            cp_commit();
        }

        // Mainloop: 32t x 32k per warp, K=128 in 8 steps, single fp16 pass
        float acc[2][4][4];
        #pragma unroll
        for (int f = 0; f < 2; ++f)
            #pragma unroll
            for (int g = 0; g < 4; ++g)
                #pragma unroll
                for (int j = 0; j < 4; ++j) acc[f][g][j] = 0.f;

        #pragma unroll
        for (int step = 0; step < 8; ++step) {
            const int h0 = step * 16;
            unsigned ath[2][4];
            #pragma unroll
            for (int f = 0; f < 2; ++f) {
                unsigned addr = thb + ((tw0 + f * 16 + rL) * PAD + h0 + cL) * 2;
                ldsm_x4(addr, ath[f][0], ath[f][1], ath[f][2], ath[f][3]);
            }
            #pragma unroll
            for (int g = 0; g < 2; ++g) {
                const int nA = kq + g * 16;
                unsigned bh0, bh1, bh2, bh3;
                unsigned baddr = smem_u32 + OFF_WHI + ((h0 + rL) * PAD + nA + cL) * 2;
                ldsm_x4_t(baddr, bh0, bh1, bh2, bh3);
                #pragma unroll
                for (int f = 0; f < 2; ++f) {
                    mma16816(acc[f][2 * g],     ath[f], bh0, bh1);
                    mma16816(acc[f][2 * g + 1], ath[f], bh2, bh3);
                }
            }
        }

        // Epilogue: packed f32x2 gelu + W2-dot, quad-reduce, psum, softsign.
        #pragma unroll
        for (int f = 0; f < 2; ++f) {
            #pragma unroll
            for (int hf = 0; hf < 2; ++hf) {
                const int t = tw0 + f * 16 + (lane >> 2) + hf * 8;
                u64 pt2 = 0ULL;
                #pragma unroll
                for (int g = 0; g < 4; ++g) {
                    u64 x2 = pk2(acc[f][g][hf * 2 + 0], acc[f][g][hf * 2 + 1]);
                    x2 = f2x_add(x2, asr2[g]);
                    const u64 ax2 = x2 & 0x7FFFFFFF7FFFFFFFULL;
                    const u64 d2 = f2x_fma(C_A, ax2, C_1);
                    const u64 s2 = f2x_mul(ax2, ax2);
                    const u64 y2 = f2x_mul(s2, C_NL);
                    float dl, dh;  upk2(dl, dh, d2);
                    const u64 t2 = pk2(rcp_ap(dl), rcp_ap(dh));
                    float yl, yh;  upk2(yl, yh, y2);
                    const u64 e2 = pk2(ex2_ap(yl), ex2_ap(yh));
                    u64 p2 = f2x_fma(C_K1, t2, C_K2);
                    p2 = f2x_fma(p2, t2, C_K3);
                    p2 = f2x_mul(p2, t2);
                    const u64 m2 = f2x_mul(p2, e2);
                    const u64 q2 = f2x_mul(ax2, C_H);
                    const u64 bb = f2x_fma(x2, C_H, q2);
                    const u64 r2 = f2x_fma(m2, q2, bb);
                    pt2 = f2x_fma(r2, w2r2[g], pt2);
                }
                float plo, phi; upk2(plo, phi, pt2);
                float pt = plo + phi;
                pt += __shfl_xor_sync(0xffffffffu, pt, 1);
                pt += __shfl_xor_sync(0xffffffffu, pt, 2);
                if ((lane & 3) == 0)
                    psum[t * 4 + (wid & 3)] = pt;
            }
        }

        // Per-t-group combine: named barrier over this group's 4 warps only.
        asm volatile("bar.sync %0, 128;" :: "r"(1 + grp) : "memory");

        if (gtid < 32) {
            const int t = tw0 + gtid;
            const float4 p4 = ((const float4*)psum)[t];
            const float sc = (p4.x + p4.y) + (p4.z + p4.w) + b2v;
            const float e  = sc / (1.0f + fabsf(sc));
            out[bs * T + thalf * 256 + tt * TROWS + t] = e * mval;
        }
    }
}

// ---------------------------------------------------------------------------
extern "C" void kernel_launch(void* const* d_in, const int* in_sizes, int n_in,
                              void* d_out, int out_size)
{
    const float* sv   = (const float*)d_in[0];
    const float* tv   = (const float*)d_in[1];
    const int*   mask = (const int*)d_in[2];
    const float* sng  = (const float*)d_in[3];
    const float* snb  = (const float*)d_in[4];
    const float* tng  = (const float*)d_in[5];
    const float* tnb  = (const float*)d_in[6];
    const float* Wsu  = (const float*)d_in[7];
    const float* bsu  = (const float*)d_in[8];
    const float* Wtp  = (const float*)d_in[9];
    const float* btp  = (const float*)d_in[10];
    const float* W1   = (const float*)d_in[11];
    const float* b1   = (const float*)d_in[12];
    const float* W2   = (const float*)d_in[13];
    const float* b2   = (const float*)d_in[14];
    float* out = (float*)d_out;

    norm_proj_kernel<<<(BS + BT) / RPB, S1THR>>>(sv, tv, sng, snb, tng, tnb,
                                                 Wsu, bsu, Wtp, btp, W1, b1);

    cudaFuncSetAttribute(edge_main_kernel,
                         cudaFuncAttributeMaxDynamicSharedMemorySize, SMEM_BYTES);
    edge_main_kernel<<<2 * BS, NTHR, SMEM_BYTES>>>(W1, W2, b2, mask, out);
}